// round 6
// baseline (speedup 1.0000x reference)
#include <cuda_runtime.h>
#include <stdint.h>

#define NUM_BINS 256
#define NCH_SAMPLE 3
#define NCH_TOTAL 6
#define NPX (2048 * 4096)
#define NREP 8   // smem histogram replicas in K1

// Static device scratch. Zeroed at module load; K2's last block restores the
// zeroed invariant (hist + ticket), so graph replays are deterministic.
__device__ int           g_hist[NCH_SAMPLE][NUM_BINS];
__device__ int           g_ticket;
__device__ unsigned char g_bins[(size_t)NCH_SAMPLE * NPX];   // 25 MB bin cache

// ───────────────────────────── K1 ─────────────────────────────
// y<3: read samples once (streaming), write uint8 bins (stay L2-dirty for K2),
//      build 8-way replicated smem hists, flush via global atomics.
// y>=3: pure streaming float4 copy of target channels (overlaps the
//       atomic-latency-bound hist blocks with bandwidth work).
__global__ void __launch_bounds__(256)
hist_copy_kernel(const float* __restrict__ img, float* __restrict__ out,
                 int npx) {
    const int c = blockIdx.y;
    const int t = threadIdx.x;
    const int stride = gridDim.x * blockDim.x;
    const int n4 = npx >> 2;

    if (c >= NCH_SAMPLE) {
        const float4* p = (const float4*)(img + (size_t)c * npx);
        float4*       q = (float4*)(out + (size_t)c * npx);
        int i = blockIdx.x * blockDim.x + t;
        for (; i + stride < n4; i += 2 * stride) {
            float4 a = __ldcs(&p[i]);
            float4 d = __ldcs(&p[i + stride]);
            __stcs(&q[i], a);
            __stcs(&q[i + stride], d);
        }
        if (i < n4) __stcs(&q[i], __ldcs(&p[i]));
        return;
    }

    __shared__ int sh[NREP][NUM_BINS];
    for (int i = t; i < NREP * NUM_BINS; i += blockDim.x) ((int*)sh)[i] = 0;
    __syncthreads();

    const float4* p = (const float4*)(img + (size_t)c * npx);
    uchar4*       b = (uchar4*)(g_bins + (size_t)c * npx);
    const int sub = t & (NREP - 1);

    int i = blockIdx.x * blockDim.x + t;
    for (; i + stride < n4; i += 2 * stride) {
        float4 v0 = __ldcs(&p[i]);
        float4 v1 = __ldcs(&p[i + stride]);
        int b0 = min(NUM_BINS - 1, max(0, (int)v0.x));
        int b1 = min(NUM_BINS - 1, max(0, (int)v0.y));
        int b2 = min(NUM_BINS - 1, max(0, (int)v0.z));
        int b3 = min(NUM_BINS - 1, max(0, (int)v0.w));
        int b4 = min(NUM_BINS - 1, max(0, (int)v1.x));
        int b5 = min(NUM_BINS - 1, max(0, (int)v1.y));
        int b6 = min(NUM_BINS - 1, max(0, (int)v1.z));
        int b7 = min(NUM_BINS - 1, max(0, (int)v1.w));
        b[i] = make_uchar4((unsigned char)b0, (unsigned char)b1,
                           (unsigned char)b2, (unsigned char)b3);
        b[i + stride] = make_uchar4((unsigned char)b4, (unsigned char)b5,
                                    (unsigned char)b6, (unsigned char)b7);
        atomicAdd(&sh[sub][b0], 1);
        atomicAdd(&sh[sub][b1], 1);
        atomicAdd(&sh[sub][b2], 1);
        atomicAdd(&sh[sub][b3], 1);
        atomicAdd(&sh[sub][b4], 1);
        atomicAdd(&sh[sub][b5], 1);
        atomicAdd(&sh[sub][b6], 1);
        atomicAdd(&sh[sub][b7], 1);
    }
    if (i < n4) {
        float4 v = __ldcs(&p[i]);
        int b0 = min(NUM_BINS - 1, max(0, (int)v.x));
        int b1 = min(NUM_BINS - 1, max(0, (int)v.y));
        int b2 = min(NUM_BINS - 1, max(0, (int)v.z));
        int b3 = min(NUM_BINS - 1, max(0, (int)v.w));
        b[i] = make_uchar4((unsigned char)b0, (unsigned char)b1,
                           (unsigned char)b2, (unsigned char)b3);
        atomicAdd(&sh[sub][b0], 1);
        atomicAdd(&sh[sub][b1], 1);
        atomicAdd(&sh[sub][b2], 1);
        atomicAdd(&sh[sub][b3], 1);
    }
    __syncthreads();

    int s = 0;
    #pragma unroll
    for (int r = 0; r < NREP; r++) s += sh[r][t];
    if (s) atomicAdd(&g_hist[c][t], s);
}

// ───────────────────────────── K2 ─────────────────────────────
// Per-block prologue: compute this channel's LUT from g_hist (256-scan),
// expand into a bank-private 32KB table (lane l always hits bank l -> zero
// LDS conflicts). Main loop: uchar4 load (L2-hot) -> 4 LDS -> float4 store.
// Ticket-elected last block resets g_hist/g_ticket for the next replay.
__global__ void __launch_bounds__(256)
apply_samples_kernel(float* __restrict__ out, int npx) {
    const int c = blockIdx.y;
    const int t = threadIdx.x;
    const int lane = t & 31;

    __shared__ float lut32[NUM_BINS][32];    // 32 KB, bank-private reads
    __shared__ int hist[NUM_BINS];
    __shared__ int cum[NUM_BINS];
    __shared__ int s_lastnz;

    // ---- LUT prologue (exact torchvision/JAX math) ----
    {
        int h = __ldcg(&g_hist[c][t]);
        hist[t] = h;
        cum[t] = h;
        if (t == 0) s_lastnz = 0;
        __syncthreads();

        #pragma unroll
        for (int off = 1; off < NUM_BINS; off <<= 1) {
            int tmp = (t >= off) ? cum[t - off] : 0;
            __syncthreads();
            cum[t] += tmp;
            __syncthreads();
        }
        if (h > 0) atomicMax(&s_lastnz, t);
        __syncthreads();

        const int total = cum[NUM_BINS - 1];
        const int step  = (total - hist[s_lastnz]) / (NUM_BINS - 1);

        float outv;
        if (step == 0) {
            outv = (float)t;                  // identity when step==0
        } else {
            int l = (t == 0) ? 0 : (cum[t - 1] + (step >> 1)) / step;
            outv = (float)min(NUM_BINS - 1, max(0, l));
        }
        // conflict-free fill of row t: bank (t+j)&31, lanes distinct
        #pragma unroll
        for (int j = 0; j < 32; j++)
            lut32[t][(t + j) & 31] = outv;
        __syncthreads();
    }

    // ---- apply ----
    const uchar4* b = (const uchar4*)(g_bins + (size_t)c * npx);
    float4*       q = (float4*)(out + (size_t)c * npx);
    const int n4 = npx >> 2;
    const int stride = gridDim.x * blockDim.x;

    int i = blockIdx.x * blockDim.x + t;
    for (; i + stride < n4; i += 2 * stride) {
        uchar4 v0 = __ldcg(&b[i]);
        uchar4 v1 = __ldcg(&b[i + stride]);
        float4 r0, r1;
        r0.x = lut32[v0.x][lane]; r0.y = lut32[v0.y][lane];
        r0.z = lut32[v0.z][lane]; r0.w = lut32[v0.w][lane];
        r1.x = lut32[v1.x][lane]; r1.y = lut32[v1.y][lane];
        r1.z = lut32[v1.z][lane]; r1.w = lut32[v1.w][lane];
        __stcs(&q[i], r0);
        __stcs(&q[i + stride], r1);
    }
    if (i < n4) {
        uchar4 v = __ldcg(&b[i]);
        float4 r;
        r.x = lut32[v.x][lane]; r.y = lut32[v.y][lane];
        r.z = lut32[v.z][lane]; r.w = lut32[v.w][lane];
        __stcs(&q[i], r);
    }

    // ---- last block resets hist + ticket for next graph replay ----
    __syncthreads();
    __shared__ int s_flag;
    if (t == 0) {
        int done = atomicAdd(&g_ticket, 1);
        s_flag = (done == (int)(gridDim.x * gridDim.y) - 1);
    }
    __syncthreads();
    if (s_flag) {
        for (int ch = 0; ch < NCH_SAMPLE; ch++) g_hist[ch][t] = 0;
        if (t == 0) g_ticket = 0;
    }
}

extern "C" void kernel_launch(void* const* d_in, const int* in_sizes, int n_in,
                              void* d_out, int out_size) {
    const float* img = (const float*)d_in[0];
    float* out = (float*)d_out;
    const int npx = in_sizes[0] / NCH_TOTAL;   // 2048*4096

    hist_copy_kernel<<<dim3(384, NCH_TOTAL), 256>>>(img, out, npx);
    apply_samples_kernel<<<dim3(344, NCH_SAMPLE), 256>>>(out, npx);
}

// round 7
// speedup vs baseline: 1.0065x; 1.0065x over previous
#include <cuda_runtime.h>
#include <stdint.h>

#define NUM_BINS 256
#define NCH_SAMPLE 3
#define NCH_TOTAL 6
#define NPX (2048 * 4096)
#define NREP 8   // smem histogram replicas in K1

// Static device scratch. Zeroed at module load; K2's last block restores the
// zeroed invariant (hist + ticket), so graph replays are deterministic.
__device__ int           g_hist[NCH_SAMPLE][NUM_BINS];
__device__ int           g_ticket;
__device__ unsigned char g_bins[(size_t)NCH_SAMPLE * NPX];   // 25 MB bin cache

// ───────────────────────────── K1 ─────────────────────────────
// y<3: read samples once (streaming), write uint8 bins (stay L2-dirty for K2),
//      build 8-way replicated smem hists, flush via global atomics.
// y>=3: pure streaming float4 copy of target channels.
__global__ void __launch_bounds__(256)
hist_copy_kernel(const float* __restrict__ img, float* __restrict__ out,
                 int npx) {
    const int c = blockIdx.y;
    const int t = threadIdx.x;
    const int stride = gridDim.x * blockDim.x;
    const int n4 = npx >> 2;

    if (c >= NCH_SAMPLE) {
        const float4* p = (const float4*)(img + (size_t)c * npx);
        float4*       q = (float4*)(out + (size_t)c * npx);
        int i = blockIdx.x * blockDim.x + t;
        for (; i + stride < n4; i += 2 * stride) {
            float4 a = __ldcs(&p[i]);
            float4 d = __ldcs(&p[i + stride]);
            __stcs(&q[i], a);
            __stcs(&q[i + stride], d);
        }
        if (i < n4) __stcs(&q[i], __ldcs(&p[i]));
        return;
    }

    __shared__ int sh[NREP][NUM_BINS];
    for (int i = t; i < NREP * NUM_BINS; i += blockDim.x) ((int*)sh)[i] = 0;
    __syncthreads();

    const float4* p = (const float4*)(img + (size_t)c * npx);
    uchar4*       b = (uchar4*)(g_bins + (size_t)c * npx);
    const int sub = t & (NREP - 1);

    int i = blockIdx.x * blockDim.x + t;
    for (; i + stride < n4; i += 2 * stride) {
        float4 v0 = __ldcs(&p[i]);
        float4 v1 = __ldcs(&p[i + stride]);
        int b0 = min(NUM_BINS - 1, max(0, (int)v0.x));
        int b1 = min(NUM_BINS - 1, max(0, (int)v0.y));
        int b2 = min(NUM_BINS - 1, max(0, (int)v0.z));
        int b3 = min(NUM_BINS - 1, max(0, (int)v0.w));
        int b4 = min(NUM_BINS - 1, max(0, (int)v1.x));
        int b5 = min(NUM_BINS - 1, max(0, (int)v1.y));
        int b6 = min(NUM_BINS - 1, max(0, (int)v1.z));
        int b7 = min(NUM_BINS - 1, max(0, (int)v1.w));
        b[i] = make_uchar4((unsigned char)b0, (unsigned char)b1,
                           (unsigned char)b2, (unsigned char)b3);
        b[i + stride] = make_uchar4((unsigned char)b4, (unsigned char)b5,
                                    (unsigned char)b6, (unsigned char)b7);
        atomicAdd(&sh[sub][b0], 1);
        atomicAdd(&sh[sub][b1], 1);
        atomicAdd(&sh[sub][b2], 1);
        atomicAdd(&sh[sub][b3], 1);
        atomicAdd(&sh[sub][b4], 1);
        atomicAdd(&sh[sub][b5], 1);
        atomicAdd(&sh[sub][b6], 1);
        atomicAdd(&sh[sub][b7], 1);
    }
    if (i < n4) {
        float4 v = __ldcs(&p[i]);
        int b0 = min(NUM_BINS - 1, max(0, (int)v.x));
        int b1 = min(NUM_BINS - 1, max(0, (int)v.y));
        int b2 = min(NUM_BINS - 1, max(0, (int)v.z));
        int b3 = min(NUM_BINS - 1, max(0, (int)v.w));
        b[i] = make_uchar4((unsigned char)b0, (unsigned char)b1,
                           (unsigned char)b2, (unsigned char)b3);
        atomicAdd(&sh[sub][b0], 1);
        atomicAdd(&sh[sub][b1], 1);
        atomicAdd(&sh[sub][b2], 1);
        atomicAdd(&sh[sub][b3], 1);
    }
    __syncthreads();

    int s = 0;
    #pragma unroll
    for (int r = 0; r < NREP; r++) s += sh[r][t];
    if (s) atomicAdd(&g_hist[c][t], s);
}

// ───────────────────────────── K2 ─────────────────────────────
// Cheap per-block LUT prologue (shfl scans, ~4 barriers), then R5's winning
// memory shape: uchar4 __ldcg (L2-hot) -> 4 smem LDS -> float4 __stcs.
// Last block (ticket) resets g_hist/g_ticket for the next graph replay.
__global__ void __launch_bounds__(256)
apply_samples_kernel(float* __restrict__ out, int npx) {
    const int c = blockIdx.y;
    const int t = threadIdx.x;
    const int lane = t & 31;
    const int w = t >> 5;

    __shared__ float lut[NUM_BINS];
    __shared__ int   shist[NUM_BINS];
    __shared__ int   scum[NUM_BINS];
    __shared__ int   wsum[8];
    __shared__ int   s_lastnz;

    // ---- fast LUT prologue (exact torchvision/JAX math) ----
    {
        int h = __ldcg(&g_hist[c][t]);
        shist[t] = h;
        if (t == 0) s_lastnz = 0;

        // warp inclusive scan
        int v = h;
        #pragma unroll
        for (int d = 1; d < 32; d <<= 1) {
            int n = __shfl_up_sync(0xffffffffu, v, d);
            if (lane >= d) v += n;
        }
        if (lane == 31) wsum[w] = v;

        // per-warp last-nonzero -> block max (1 atomic per warp)
        unsigned bal = __ballot_sync(0xffffffffu, h > 0);
        if (bal && lane == (31 - __clz(bal))) atomicMax(&s_lastnz, t);
        __syncthreads();

        // warp 0: inclusive scan of the 8 warp sums
        if (w == 0 && lane < 8) {
            int x = wsum[lane];
            #pragma unroll
            for (int d = 1; d < 8; d <<= 1) {
                int n = __shfl_up_sync(0x000000ffu, x, d);
                if (lane >= d) x += n;
            }
            wsum[lane] = x;
        }
        __syncthreads();

        int cum = v + (w > 0 ? wsum[w - 1] : 0);   // inclusive cumsum
        scum[t] = cum;
        __syncthreads();

        const int total = wsum[7];
        const int last  = s_lastnz;
        const int step  = (total - shist[last]) / (NUM_BINS - 1);

        float outv;
        if (step == 0) {
            outv = (float)t;                       // identity when step==0
        } else {
            int l = (t == 0) ? 0 : (scum[t - 1] + (step >> 1)) / step;
            outv = (float)min(NUM_BINS - 1, max(0, l));
        }
        lut[t] = outv;
        __syncthreads();
    }

    // ---- apply ----
    const uchar4* b = (const uchar4*)(g_bins + (size_t)c * npx);
    float4*       q = (float4*)(out + (size_t)c * npx);
    const int n4 = npx >> 2;
    const int stride = gridDim.x * blockDim.x;

    int i = blockIdx.x * blockDim.x + t;
    for (; i + stride < n4; i += 2 * stride) {
        uchar4 v0 = __ldcg(&b[i]);
        uchar4 v1 = __ldcg(&b[i + stride]);
        float4 r0, r1;
        r0.x = lut[v0.x]; r0.y = lut[v0.y]; r0.z = lut[v0.z]; r0.w = lut[v0.w];
        r1.x = lut[v1.x]; r1.y = lut[v1.y]; r1.z = lut[v1.z]; r1.w = lut[v1.w];
        __stcs(&q[i], r0);
        __stcs(&q[i + stride], r1);
    }
    if (i < n4) {
        uchar4 v = __ldcg(&b[i]);
        float4 r;
        r.x = lut[v.x]; r.y = lut[v.y]; r.z = lut[v.z]; r.w = lut[v.w];
        __stcs(&q[i], r);
    }

    // ---- last block resets hist + ticket for next graph replay ----
    __syncthreads();
    __shared__ int s_flag;
    if (t == 0) {
        int done = atomicAdd(&g_ticket, 1);
        s_flag = (done == (int)(gridDim.x * gridDim.y) - 1);
    }
    __syncthreads();
    if (s_flag) {
        for (int ch = 0; ch < NCH_SAMPLE; ch++) g_hist[ch][t] = 0;
        if (t == 0) g_ticket = 0;
    }
}

extern "C" void kernel_launch(void* const* d_in, const int* in_sizes, int n_in,
                              void* d_out, int out_size) {
    const float* img = (const float*)d_in[0];
    float* out = (float*)d_out;
    const int npx = in_sizes[0] / NCH_TOTAL;   // 2048*4096

    hist_copy_kernel<<<dim3(384, NCH_TOTAL), 256>>>(img, out, npx);
    apply_samples_kernel<<<dim3(1024, NCH_SAMPLE), 256>>>(out, npx);
}

// round 8
// speedup vs baseline: 1.0069x; 1.0004x over previous
#include <cuda_runtime.h>
#include <stdint.h>

#define NUM_BINS 256
#define NCH_SAMPLE 3
#define NCH_TOTAL 6
#define NPX (2048 * 4096)
#define NREP 8   // smem histogram replicas in K1

// Static device scratch. Zeroed at module load; K2's last block restores the
// zeroed invariant (hist + ticket), so graph replays are deterministic.
__device__ int           g_hist[NCH_SAMPLE][NUM_BINS];
__device__ int           g_ticket;
__device__ unsigned char g_bins[(size_t)NCH_SAMPLE * NPX];   // 25 MB bin cache

// ───────────────────────────── K1 ─────────────────────────────
// y<3: read samples once (streaming), write uint8 bins (stay L2-dirty for K2),
//      build 8-way replicated smem hists, flush via global atomics.
// y>=3: pure streaming float4 copy of target channels.
__global__ void __launch_bounds__(256)
hist_copy_kernel(const float* __restrict__ img, float* __restrict__ out,
                 int npx) {
    const int c = blockIdx.y;
    const int t = threadIdx.x;
    const int stride = gridDim.x * blockDim.x;
    const int n4 = npx >> 2;

    if (c >= NCH_SAMPLE) {
        const float4* p = (const float4*)(img + (size_t)c * npx);
        float4*       q = (float4*)(out + (size_t)c * npx);
        int i = blockIdx.x * blockDim.x + t;
        for (; i + stride < n4; i += 2 * stride) {
            float4 a = __ldcs(&p[i]);
            float4 d = __ldcs(&p[i + stride]);
            __stcs(&q[i], a);
            __stcs(&q[i + stride], d);
        }
        if (i < n4) __stcs(&q[i], __ldcs(&p[i]));
        return;
    }

    __shared__ int sh[NREP][NUM_BINS];
    for (int i = t; i < NREP * NUM_BINS; i += blockDim.x) ((int*)sh)[i] = 0;
    __syncthreads();

    const float4* p = (const float4*)(img + (size_t)c * npx);
    uchar4*       b = (uchar4*)(g_bins + (size_t)c * npx);
    const int sub = t & (NREP - 1);

    int i = blockIdx.x * blockDim.x + t;
    for (; i + stride < n4; i += 2 * stride) {
        float4 v0 = __ldcs(&p[i]);
        float4 v1 = __ldcs(&p[i + stride]);
        int b0 = min(NUM_BINS - 1, max(0, (int)v0.x));
        int b1 = min(NUM_BINS - 1, max(0, (int)v0.y));
        int b2 = min(NUM_BINS - 1, max(0, (int)v0.z));
        int b3 = min(NUM_BINS - 1, max(0, (int)v0.w));
        int b4 = min(NUM_BINS - 1, max(0, (int)v1.x));
        int b5 = min(NUM_BINS - 1, max(0, (int)v1.y));
        int b6 = min(NUM_BINS - 1, max(0, (int)v1.z));
        int b7 = min(NUM_BINS - 1, max(0, (int)v1.w));
        b[i] = make_uchar4((unsigned char)b0, (unsigned char)b1,
                           (unsigned char)b2, (unsigned char)b3);
        b[i + stride] = make_uchar4((unsigned char)b4, (unsigned char)b5,
                                    (unsigned char)b6, (unsigned char)b7);
        atomicAdd(&sh[sub][b0], 1);
        atomicAdd(&sh[sub][b1], 1);
        atomicAdd(&sh[sub][b2], 1);
        atomicAdd(&sh[sub][b3], 1);
        atomicAdd(&sh[sub][b4], 1);
        atomicAdd(&sh[sub][b5], 1);
        atomicAdd(&sh[sub][b6], 1);
        atomicAdd(&sh[sub][b7], 1);
    }
    if (i < n4) {
        float4 v = __ldcs(&p[i]);
        int b0 = min(NUM_BINS - 1, max(0, (int)v.x));
        int b1 = min(NUM_BINS - 1, max(0, (int)v.y));
        int b2 = min(NUM_BINS - 1, max(0, (int)v.z));
        int b3 = min(NUM_BINS - 1, max(0, (int)v.w));
        b[i] = make_uchar4((unsigned char)b0, (unsigned char)b1,
                           (unsigned char)b2, (unsigned char)b3);
        atomicAdd(&sh[sub][b0], 1);
        atomicAdd(&sh[sub][b1], 1);
        atomicAdd(&sh[sub][b2], 1);
        atomicAdd(&sh[sub][b3], 1);
    }
    __syncthreads();

    int s = 0;
    #pragma unroll
    for (int r = 0; r < NREP; r++) s += sh[r][t];
    if (s) atomicAdd(&g_hist[c][t], s);
}

// ───────────────────────────── K2 ─────────────────────────────
// One-wave grid: each resident CTA pays the LUT prologue exactly once.
// Prologue: shfl-scan LUT (race fixed: barrier between s_lastnz init and
// the atomicMax). Main loop: uchar4 __ldcg (L2-hot) -> 4 LDS -> float4 __stcs.
// Last block (ticket) resets g_hist/g_ticket for the next graph replay.
__global__ void __launch_bounds__(256)
apply_samples_kernel(float* __restrict__ out, int npx) {
    const int c = blockIdx.y;
    const int t = threadIdx.x;
    const int lane = t & 31;
    const int w = t >> 5;

    __shared__ float lut[NUM_BINS];
    __shared__ int   shist[NUM_BINS];
    __shared__ int   scum[NUM_BINS];
    __shared__ int   wsum[8];
    __shared__ int   s_lastnz;

    // ---- LUT prologue (exact torchvision/JAX math) ----
    {
        if (t == 0) s_lastnz = 0;
        int h = __ldcg(&g_hist[c][t]);
        shist[t] = h;
        __syncthreads();                      // init visible before atomicMax

        // warp inclusive scan
        int v = h;
        #pragma unroll
        for (int d = 1; d < 32; d <<= 1) {
            int n = __shfl_up_sync(0xffffffffu, v, d);
            if (lane >= d) v += n;
        }
        if (lane == 31) wsum[w] = v;

        // per-warp last-nonzero -> block max (1 atomic per warp)
        unsigned bal = __ballot_sync(0xffffffffu, h > 0);
        if (bal && lane == (31 - __clz(bal))) atomicMax(&s_lastnz, t);
        __syncthreads();

        // warp 0: inclusive scan of the 8 warp sums
        if (w == 0 && lane < 8) {
            int x = wsum[lane];
            #pragma unroll
            for (int d = 1; d < 8; d <<= 1) {
                int n = __shfl_up_sync(0x000000ffu, x, d);
                if (lane >= d) x += n;
            }
            wsum[lane] = x;
        }
        __syncthreads();

        int cum = v + (w > 0 ? wsum[w - 1] : 0);   // inclusive cumsum
        scum[t] = cum;
        __syncthreads();

        const int total = wsum[7];
        const int last  = s_lastnz;
        const int step  = (total - shist[last]) / (NUM_BINS - 1);

        float outv;
        if (step == 0) {
            outv = (float)t;                       // identity when step==0
        } else {
            int l = (t == 0) ? 0 : (scum[t - 1] + (step >> 1)) / step;
            outv = (float)min(NUM_BINS - 1, max(0, l));
        }
        lut[t] = outv;
        __syncthreads();
    }

    // ---- apply ----
    const uchar4* b = (const uchar4*)(g_bins + (size_t)c * npx);
    float4*       q = (float4*)(out + (size_t)c * npx);
    const int n4 = npx >> 2;
    const int stride = gridDim.x * blockDim.x;

    int i = blockIdx.x * blockDim.x + t;
    for (; i + stride < n4; i += 2 * stride) {
        uchar4 v0 = __ldcg(&b[i]);
        uchar4 v1 = __ldcg(&b[i + stride]);
        float4 r0, r1;
        r0.x = lut[v0.x]; r0.y = lut[v0.y]; r0.z = lut[v0.z]; r0.w = lut[v0.w];
        r1.x = lut[v1.x]; r1.y = lut[v1.y]; r1.z = lut[v1.z]; r1.w = lut[v1.w];
        __stcs(&q[i], r0);
        __stcs(&q[i + stride], r1);
    }
    if (i < n4) {
        uchar4 v = __ldcg(&b[i]);
        float4 r;
        r.x = lut[v.x]; r.y = lut[v.y]; r.z = lut[v.z]; r.w = lut[v.w];
        __stcs(&q[i], r);
    }

    // ---- last block resets hist + ticket for next graph replay ----
    __syncthreads();
    __shared__ int s_flag;
    if (t == 0) {
        int done = atomicAdd(&g_ticket, 1);
        s_flag = (done == (int)(gridDim.x * gridDim.y) - 1);
    }
    __syncthreads();
    if (s_flag) {
        for (int ch = 0; ch < NCH_SAMPLE; ch++) g_hist[ch][t] = 0;
        if (t == 0) g_ticket = 0;
    }
}

extern "C" void kernel_launch(void* const* d_in, const int* in_sizes, int n_in,
                              void* d_out, int out_size) {
    const float* img = (const float*)d_in[0];
    float* out = (float*)d_out;
    const int npx = in_sizes[0] / NCH_TOTAL;   // 2048*4096

    hist_copy_kernel<<<dim3(384, NCH_TOTAL), 256>>>(img, out, npx);
    // one wave: 394*3 = 1182 blocks ≈ 148 SMs * 8 CTAs
    apply_samples_kernel<<<dim3(394, NCH_SAMPLE), 256>>>(out, npx);
}

// round 9
// speedup vs baseline: 1.0348x; 1.0276x over previous
#include <cuda_runtime.h>
#include <stdint.h>

#define NUM_BINS 256
#define NCH_SAMPLE 3
#define NCH_TOTAL 6
#define NPX (2048 * 4096)
#define NREP 8   // smem histogram replicas in K1

// Static device scratch. Zeroed at module load; K1's last hist block restores
// the zeroed invariant (hist + ticket), so graph replays are deterministic.
__device__ int           g_hist[NCH_SAMPLE][NUM_BINS];
__device__ float         g_lut[NCH_SAMPLE][NUM_BINS];
__device__ int           g_ticket;
__device__ unsigned char g_bins[(size_t)NCH_SAMPLE * NPX];   // 25 MB bin cache

// ───────────────────────────── K1 ─────────────────────────────
// y<3: read samples once (streaming), write uint8 bins (stay L2-dirty for K2),
//      8-way replicated smem hists, flush via global atomics. Ticket-elected
//      last hist block computes all 3 LUTs and resets hist/ticket.
// y>=3: pure streaming float4 copy of target channels (fills the bandwidth
//       the atomic-bound hist blocks leave idle).
__global__ void __launch_bounds__(256)
hist_copy_kernel(const float* __restrict__ img, float* __restrict__ out,
                 int npx) {
    const int c = blockIdx.y;
    const int t = threadIdx.x;
    const int stride = gridDim.x * blockDim.x;
    const int n4 = npx >> 2;

    if (c >= NCH_SAMPLE) {
        const float4* p = (const float4*)(img + (size_t)c * npx);
        float4*       q = (float4*)(out + (size_t)c * npx);
        int i = blockIdx.x * blockDim.x + t;
        for (; i + stride < n4; i += 2 * stride) {
            float4 a = __ldcs(&p[i]);
            float4 d = __ldcs(&p[i + stride]);
            __stcs(&q[i], a);
            __stcs(&q[i + stride], d);
        }
        if (i < n4) __stcs(&q[i], __ldcs(&p[i]));
        return;
    }

    __shared__ int sh[NREP][NUM_BINS];
    __shared__ int s_flag;
    for (int i = t; i < NREP * NUM_BINS; i += blockDim.x) ((int*)sh)[i] = 0;
    __syncthreads();

    const float4* p = (const float4*)(img + (size_t)c * npx);
    uchar4*       b = (uchar4*)(g_bins + (size_t)c * npx);
    const int sub = t & (NREP - 1);

    int i = blockIdx.x * blockDim.x + t;
    for (; i + stride < n4; i += 2 * stride) {
        float4 v0 = __ldcs(&p[i]);
        float4 v1 = __ldcs(&p[i + stride]);
        int b0 = min(NUM_BINS - 1, max(0, (int)v0.x));
        int b1 = min(NUM_BINS - 1, max(0, (int)v0.y));
        int b2 = min(NUM_BINS - 1, max(0, (int)v0.z));
        int b3 = min(NUM_BINS - 1, max(0, (int)v0.w));
        int b4 = min(NUM_BINS - 1, max(0, (int)v1.x));
        int b5 = min(NUM_BINS - 1, max(0, (int)v1.y));
        int b6 = min(NUM_BINS - 1, max(0, (int)v1.z));
        int b7 = min(NUM_BINS - 1, max(0, (int)v1.w));
        b[i] = make_uchar4((unsigned char)b0, (unsigned char)b1,
                           (unsigned char)b2, (unsigned char)b3);
        b[i + stride] = make_uchar4((unsigned char)b4, (unsigned char)b5,
                                    (unsigned char)b6, (unsigned char)b7);
        atomicAdd(&sh[sub][b0], 1);
        atomicAdd(&sh[sub][b1], 1);
        atomicAdd(&sh[sub][b2], 1);
        atomicAdd(&sh[sub][b3], 1);
        atomicAdd(&sh[sub][b4], 1);
        atomicAdd(&sh[sub][b5], 1);
        atomicAdd(&sh[sub][b6], 1);
        atomicAdd(&sh[sub][b7], 1);
    }
    if (i < n4) {
        float4 v = __ldcs(&p[i]);
        int b0 = min(NUM_BINS - 1, max(0, (int)v.x));
        int b1 = min(NUM_BINS - 1, max(0, (int)v.y));
        int b2 = min(NUM_BINS - 1, max(0, (int)v.z));
        int b3 = min(NUM_BINS - 1, max(0, (int)v.w));
        b[i] = make_uchar4((unsigned char)b0, (unsigned char)b1,
                           (unsigned char)b2, (unsigned char)b3);
        atomicAdd(&sh[sub][b0], 1);
        atomicAdd(&sh[sub][b1], 1);
        atomicAdd(&sh[sub][b2], 1);
        atomicAdd(&sh[sub][b3], 1);
    }
    __syncthreads();

    int s = 0;
    #pragma unroll
    for (int r = 0; r < NREP; r++) s += sh[r][t];
    if (s) atomicAdd(&g_hist[c][t], s);

    // ---- last arriving hist block computes the LUTs ----
    __threadfence();
    if (t == 0) {
        int done = atomicAdd(&g_ticket, 1);
        s_flag = (done == (int)(gridDim.x * NCH_SAMPLE) - 1);
    }
    __syncthreads();
    if (!s_flag) return;

    __shared__ int hist[NUM_BINS];
    __shared__ int cum[NUM_BINS];
    __shared__ int s_lastnz;

    for (int ch = 0; ch < NCH_SAMPLE; ch++) {
        int h = *(volatile int*)&g_hist[ch][t];
        hist[t] = h;
        cum[t] = h;
        if (t == 0) s_lastnz = 0;
        __syncthreads();

        #pragma unroll
        for (int off = 1; off < NUM_BINS; off <<= 1) {
            int tmp = (t >= off) ? cum[t - off] : 0;
            __syncthreads();
            cum[t] += tmp;
            __syncthreads();
        }
        if (h > 0) atomicMax(&s_lastnz, t);
        __syncthreads();

        const int total = cum[NUM_BINS - 1];
        const int step  = (total - hist[s_lastnz]) / (NUM_BINS - 1);

        float outv;
        if (step == 0) {
            outv = (float)t;                  // identity when step==0
        } else {
            int l = (t == 0) ? 0 : (cum[t - 1] + (step >> 1)) / step;
            outv = (float)min(NUM_BINS - 1, max(0, l));
        }
        g_lut[ch][t] = outv;
        g_hist[ch][t] = 0;                    // reset for next graph replay
        __syncthreads();
    }
    if (t == 0) g_ticket = 0;
}

// ───────────────────────────── K2 ─────────────────────────────
// Lean apply, 4-way independent unroll for MLP: 4 uchar4 loads issued up
// front (L2-hot), 16 smem LUT gathers, 4 coalesced float4 streaming stores.
__global__ void __launch_bounds__(256)
apply_samples_kernel(float* __restrict__ out, int npx) {
    const int c = blockIdx.y;
    const int t = threadIdx.x;

    __shared__ float lut[NUM_BINS];
    for (int i = t; i < NUM_BINS; i += blockDim.x)
        lut[i] = g_lut[c][i];
    __syncthreads();

    const uchar4* b = (const uchar4*)(g_bins + (size_t)c * npx);
    float4*       q = (float4*)(out + (size_t)c * npx);
    const int n4 = npx >> 2;
    const int stride = gridDim.x * blockDim.x;

    int i = blockIdx.x * blockDim.x + t;
    for (; i + 3 * stride < n4; i += 4 * stride) {
        uchar4 v0 = __ldcg(&b[i]);
        uchar4 v1 = __ldcg(&b[i + stride]);
        uchar4 v2 = __ldcg(&b[i + 2 * stride]);
        uchar4 v3 = __ldcg(&b[i + 3 * stride]);
        float4 r0, r1, r2, r3;
        r0.x = lut[v0.x]; r0.y = lut[v0.y]; r0.z = lut[v0.z]; r0.w = lut[v0.w];
        r1.x = lut[v1.x]; r1.y = lut[v1.y]; r1.z = lut[v1.z]; r1.w = lut[v1.w];
        r2.x = lut[v2.x]; r2.y = lut[v2.y]; r2.z = lut[v2.z]; r2.w = lut[v2.w];
        r3.x = lut[v3.x]; r3.y = lut[v3.y]; r3.z = lut[v3.z]; r3.w = lut[v3.w];
        __stcs(&q[i], r0);
        __stcs(&q[i + stride], r1);
        __stcs(&q[i + 2 * stride], r2);
        __stcs(&q[i + 3 * stride], r3);
    }
    for (; i < n4; i += stride) {
        uchar4 v = __ldcg(&b[i]);
        float4 r;
        r.x = lut[v.x]; r.y = lut[v.y]; r.z = lut[v.z]; r.w = lut[v.w];
        __stcs(&q[i], r);
    }
}

extern "C" void kernel_launch(void* const* d_in, const int* in_sizes, int n_in,
                              void* d_out, int out_size) {
    const float* img = (const float*)d_in[0];
    float* out = (float*)d_out;
    const int npx = in_sizes[0] / NCH_TOTAL;   // 2048*4096

    hist_copy_kernel<<<dim3(384, NCH_TOTAL), 256>>>(img, out, npx);
    apply_samples_kernel<<<dim3(1024, NCH_SAMPLE), 256>>>(out, npx);
}

// round 10
// speedup vs baseline: 1.0841x; 1.0476x over previous
#include <cuda_runtime.h>
#include <stdint.h>

#define NUM_BINS 256
#define NCH_SAMPLE 3
#define NCH_TOTAL 6
#define NPX (2048 * 4096)

#define SLICES 197                 // slices per channel
#define NCTAS (SLICES * 3)         // 591 CTAs total (<= 148 SMs * 4 resident)
#define GPC 10646                  // float4 groups per CTA: ceil(2097152/197)

// Static device scratch (zeroed at load; last-done CTA restores zeros each
// run, so graph replays are deterministic).
__device__ int g_hist[NCH_SAMPLE][NUM_BINS];
__device__ int g_ticket;
__device__ int g_done;

// Single persistent kernel:
//  A: hist + binize own sample slice (bins kept in smem)
//  B: grid-stride copy of target channels (hides the hist sync)
//  C: spin on ticket, build own channel's LUT
//  D: apply LUT from smem bins -> output
__global__ void __launch_bounds__(256, 4)
equalize_fused_kernel(const float* __restrict__ img,
                      float* __restrict__ out, int npx) {
    const int t = threadIdx.x;
    const int c  = blockIdx.x % NCH_SAMPLE;     // channel
    const int sl = blockIdx.x / NCH_SAMPLE;     // slice within channel
    const int n4 = npx >> 2;
    const int base = sl * GPC;
    const int end  = min(base + GPC, n4);

    __shared__ uint32_t s_bins[GPC];            // 42584 B packed bins
    __shared__ int      s_hist[4][NUM_BINS];    // 4 KB replicas / scan scratch
    __shared__ float    s_lut[NUM_BINS];        // 1 KB
    __shared__ int      s_lastnz;

    // ---- Phase A: hist + binize (sample read happens exactly once) ----
    for (int i = t; i < 4 * NUM_BINS; i += blockDim.x) ((int*)s_hist)[i] = 0;
    __syncthreads();

    {
        const float4* p = (const float4*)(img + (size_t)c * npx);
        const int sub = t & 3;
        #pragma unroll 4
        for (int g = base + t; g < end; g += 256) {
            float4 v = __ldcs(&p[g]);
            int b0 = min(NUM_BINS - 1, max(0, (int)v.x));
            int b1 = min(NUM_BINS - 1, max(0, (int)v.y));
            int b2 = min(NUM_BINS - 1, max(0, (int)v.z));
            int b3 = min(NUM_BINS - 1, max(0, (int)v.w));
            s_bins[g - base] = (uint32_t)b0 | ((uint32_t)b1 << 8) |
                               ((uint32_t)b2 << 16) | ((uint32_t)b3 << 24);
            atomicAdd(&s_hist[sub][b0], 1);
            atomicAdd(&s_hist[sub][b1], 1);
            atomicAdd(&s_hist[sub][b2], 1);
            atomicAdd(&s_hist[sub][b3], 1);
        }
    }
    __syncthreads();
    {
        int s = s_hist[0][t] + s_hist[1][t] + s_hist[2][t] + s_hist[3][t];
        if (s) atomicAdd(&g_hist[c][t], s);
    }
    __threadfence();                            // release hist before arrive
    if (t == 0) atomicAdd(&g_ticket, 1);

    // ---- Phase B: target copy (overlaps / hides the global hist sync) ----
    {
        const float4* p = (const float4*)(img + (size_t)NCH_SAMPLE * npx);
        float4*       q = (float4*)(out + (size_t)NCH_SAMPLE * npx);
        const int tn4 = NCH_SAMPLE * n4;
        const int stride = NCTAS * 256;
        int i = blockIdx.x * 256 + t;
        for (; i + stride < tn4; i += 2 * stride) {
            float4 a = __ldcs(&p[i]);
            float4 d = __ldcs(&p[i + stride]);
            __stcs(&q[i], a);
            __stcs(&q[i + stride], d);
        }
        if (i < tn4) __stcs(&q[i], __ldcs(&p[i]));
    }

    // ---- Phase C: wait for all hist arrivals, then build this channel's LUT
    if (t == 0) {
        while (*(volatile int*)&g_ticket != NCTAS) __nanosleep(128);
    }
    __syncthreads();
    __threadfence();

    {
        int* hist = s_hist[0];
        int* cum  = s_hist[1];
        int h = __ldcg(&g_hist[c][t]);
        hist[t] = h;
        cum[t]  = h;
        if (t == 0) s_lastnz = 0;
        __syncthreads();

        #pragma unroll
        for (int off = 1; off < NUM_BINS; off <<= 1) {
            int tmp = (t >= off) ? cum[t - off] : 0;
            __syncthreads();
            cum[t] += tmp;
            __syncthreads();
        }
        if (h > 0) atomicMax(&s_lastnz, t);
        __syncthreads();

        const int total = cum[NUM_BINS - 1];
        const int step  = (total - hist[s_lastnz]) / (NUM_BINS - 1);

        float outv;
        if (step == 0) {
            outv = (float)t;                    // identity when step==0
        } else {
            int l = (t == 0) ? 0 : (cum[t - 1] + (step >> 1)) / step;
            outv = (float)min(NUM_BINS - 1, max(0, l));
        }
        s_lut[t] = outv;
        __syncthreads();
    }

    // ---- Phase D: apply from smem bins (no global re-read of samples) ----
    {
        float4* q = (float4*)(out + (size_t)c * npx);
        #pragma unroll 4
        for (int g = base + t; g < end; g += 256) {
            uint32_t w = s_bins[g - base];
            float4 r;
            r.x = s_lut[w & 255];
            r.y = s_lut[(w >> 8) & 255];
            r.z = s_lut[(w >> 16) & 255];
            r.w = s_lut[w >> 24];
            __stcs(&q[g], r);
        }
    }

    // ---- reset shared state for next graph replay (last-done CTA) ----
    __syncthreads();
    __shared__ int s_last;
    if (t == 0) {
        int d = atomicAdd(&g_done, 1);
        s_last = (d == NCTAS - 1);
    }
    __syncthreads();
    if (s_last) {
        g_hist[0][t] = 0;
        g_hist[1][t] = 0;
        g_hist[2][t] = 0;
        if (t == 0) { g_ticket = 0; g_done = 0; }
    }
}

extern "C" void kernel_launch(void* const* d_in, const int* in_sizes, int n_in,
                              void* d_out, int out_size) {
    const float* img = (const float*)d_in[0];
    float* out = (float*)d_out;
    const int npx = in_sizes[0] / NCH_TOTAL;   // 2048*4096

    equalize_fused_kernel<<<NCTAS, 256>>>(img, out, npx);
}